// round 6
// baseline (speedup 1.0000x reference)
#include <cuda_runtime.h>
#include <cstdint>

#define SEQ   4096
#define BATCH 4
#define DIM   1024
#define RANK  64
#define NROW  (BATCH * SEQ)   // 16384
#define NTILE 32
#define TRI   528             // upper-tri tiles per batch

#define PREP_N 64
#define PROJ_N 256
#define DIST_N (TRI * BATCH)  // 2112
#define TOTAL_W (PREP_N + PROJ_N + DIST_N)

// Scratch (__device__ globals per allocation rules)
__device__ float g_pA[NROW * RANK];
__device__ float g_pB[NROW * RANK];
__device__ float g_sq[NROW];
__device__ float g_pf[DIM * RANK];
__device__ int   g_work;
__device__ int   g_done[129];   // [0..127] proj 128-row block counters, [128] prep

// ---------------- helpers ----------------
__device__ __forceinline__ uint32_t smem_u32(const void* p) {
    uint32_t a;
    asm("{ .reg .u64 t; cvta.to.shared.u64 t, %1; cvt.u32.u64 %0, t; }"
        : "=r"(a) : "l"(p));
    return a;
}
__device__ __forceinline__ void cpasync16(uint32_t s, const void* g) {
    asm volatile("cp.async.cg.shared.global [%0], [%1], 16;"
                 :: "r"(s), "l"(g) : "memory");
}
__device__ __forceinline__ uint32_t tf32u(float f) {
    uint32_t t;
    asm("cvt.rna.tf32.f32 %0, %1;" : "=r"(t) : "f"(f));
    return t;
}
__device__ __forceinline__ float tf32r(float f) { return __uint_as_float(tf32u(f)); }
__device__ __forceinline__ void mma_tf32(float* d, const uint32_t* a,
                                         uint32_t b0, uint32_t b1) {
    asm volatile(
        "mma.sync.aligned.m16n8k8.row.col.f32.tf32.tf32.f32 "
        "{%0,%1,%2,%3}, {%4,%5,%6,%7}, {%8,%9}, {%0,%1,%2,%3};"
        : "+f"(d[0]), "+f"(d[1]), "+f"(d[2]), "+f"(d[3])
        : "r"(a[0]), "r"(a[1]), "r"(a[2]), "r"(a[3]), "r"(b0), "r"(b1));
}
__device__ __forceinline__ int ld_acq(const int* p) {
    int v;
    asm volatile("ld.acquire.gpu.global.b32 %0, [%1];" : "=r"(v) : "l"(p));
    return v;
}
__device__ __forceinline__ void npause() {
    asm volatile("nanosleep.u32 64;");
}

// ---------------- sizes ----------------
#define XST 68
#define XBUF (64 * XST)
#define PBUF 4096
#define STAGE (XBUF + PBUF)            // 8448 floats
#define FUSED_SMEM (3 * STAGE * 4)     // 101376 B (covers dist's 71680 too)
#define TS_STRIDE 140

// ============================================================
// reset kernel: zero work counter + done flags (each launch)
// ============================================================
__global__ void reset_kernel() {
    int t = threadIdx.x;
    if (t < 129) g_done[t] = 0;
    if (t == 129) g_work = 0;
}

// ============================================================
// fused persistent kernel
// ============================================================
__global__ void __launch_bounds__(256, 2) fused_kernel(
    const float* __restrict__ x, const float* __restrict__ proj,
    float* __restrict__ out) {
    extern __shared__ __align__(16) float smf[];
    __shared__ int s_id;
    __shared__ float s_part[2][64];
    __shared__ float s_sqA[128], s_sqB[128];

    const int tid = threadIdx.x, wid = tid >> 5, lane = tid & 31;
    const int gid = lane >> 2, tig = lane & 3;
    const uint32_t sbase = smem_u32(smf);

    for (;;) {
        if (tid == 0) s_id = atomicAdd(&g_work, 1);
        __syncthreads();
        const int w = s_id;
        __syncthreads();
        if (w >= TOTAL_W) return;

        if (w < PREP_N) {
            // ---------------- prep: proj -> tf32 B-fragment chunks ----------
            int idx = w * 256 + tid;
            int k = idx >> 4, n4 = (idx & 15) << 2;
            float4 v = *(const float4*)(proj + (size_t)k * RANK + n4);
            int chunk = k >> 6, kk = k & 63;
            int kt = kk >> 3, f = (kk >> 2) & 1, k3 = kk & 3;
            float* dst = g_pf + chunk * 4096;
            const float* vp = (const float*)&v;
#pragma unroll
            for (int j = 0; j < 4; j++) {
                int n = n4 + j;
                dst[((n >> 3) * 8 + kt) * 64 + ((n & 7) * 4 + k3) * 2 + f] =
                    tf32r(vp[j]);
            }
            __syncthreads();
            if (tid == 0) {
                __threadfence();
                atomicAdd(&g_done[128], 1);
            }
            __syncthreads();

        } else if (w < PREP_N + PROJ_N) {
            // ---------------- proj: 64-row chunk, K=1024, 3-stage pipeline ---
            const int item = w - PREP_N;
            const int rowbase = item * 64;
            const int wm = wid & 3, wn = wid >> 2;

            if (tid == 0) {
                while (ld_acq(&g_done[128]) < PREP_N) npause();
            }
            __syncthreads();

            float acc[4][4];
#pragma unroll
            for (int a = 0; a < 4; a++)
#pragma unroll
                for (int b = 0; b < 4; b++) acc[a][b] = 0.f;

            auto load_stage = [&](int it, int buf) {
                const uint32_t sb = sbase + (uint32_t)(buf * STAGE) * 4;
                const float* src = x + (size_t)rowbase * DIM + it * 64;
#pragma unroll
                for (int l = 0; l < 4; l++) {
                    int idx = tid + l * 256;
                    int r = idx >> 4, c4 = (idx & 15) << 2;
                    cpasync16(sb + (uint32_t)(r * XST + c4) * 4,
                              src + (size_t)r * DIM + c4);
                }
                const float* pf = g_pf + it * PBUF;
#pragma unroll
                for (int l = 0; l < 4; l++) {
                    int idx = tid + l * 256;
                    cpasync16(sb + (uint32_t)(XBUF + idx * 4) * 4, pf + idx * 4);
                }
                asm volatile("cp.async.commit_group;" ::: "memory");
            };

            load_stage(0, 0);
            load_stage(1, 1);
            load_stage(2, 2);

            int buf = 0;
            for (int it = 0; it < 16; ++it) {
                if (it <= 13)
                    asm volatile("cp.async.wait_group 2;" ::: "memory");
                else if (it == 14)
                    asm volatile("cp.async.wait_group 1;" ::: "memory");
                else
                    asm volatile("cp.async.wait_group 0;" ::: "memory");
                __syncthreads();

                const float* xb = smf + buf * STAGE;
                const float* pb = xb + XBUF;
                const int r0 = wm * 16 + gid;
#pragma unroll
                for (int kt = 0; kt < 8; kt++) {
                    const int c = kt * 8 + tig;
                    uint32_t a[4];
                    a[0] = tf32u(xb[r0 * XST + c]);
                    a[1] = tf32u(xb[(r0 + 8) * XST + c]);
                    a[2] = tf32u(xb[r0 * XST + c + 4]);
                    a[3] = tf32u(xb[(r0 + 8) * XST + c + 4]);
#pragma unroll
                    for (int nt = 0; nt < 4; nt++) {
                        const int ng = wn * 4 + nt;
                        const uint2 bb =
                            *(const uint2*)(pb + (ng * 8 + kt) * 64 + lane * 2);
                        mma_tf32(acc[nt], a, bb.x, bb.y);
                    }
                }
                __syncthreads();
                if (it + 3 < 16) load_stage(it + 3, buf);
                buf = (buf == 2) ? 0 : buf + 1;
            }

            // epilogue
            float vals[4][4];
            float sq1 = 0.f, sq2 = 0.f;
#pragma unroll
            for (int nt = 0; nt < 4; nt++) {
#pragma unroll
                for (int jj = 0; jj < 4; jj++) vals[nt][jj] = tf32r(acc[nt][jj]);
                sq1 += vals[nt][0] * vals[nt][0] + vals[nt][1] * vals[nt][1];
                sq2 += vals[nt][2] * vals[nt][2] + vals[nt][3] * vals[nt][3];
            }
            sq1 += __shfl_xor_sync(0xffffffffu, sq1, 1);
            sq1 += __shfl_xor_sync(0xffffffffu, sq1, 2);
            sq2 += __shfl_xor_sync(0xffffffffu, sq2, 1);
            sq2 += __shfl_xor_sync(0xffffffffu, sq2, 2);

            const int r1 = wm * 16 + gid, r2 = r1 + 8;
            if (tig == 0) {
                s_part[wn][r1] = sq1;
                s_part[wn][r2] = sq2;
            }
            __syncthreads();
            if (tid < 64) g_sq[rowbase + tid] = s_part[0][tid] + s_part[1][tid];

            const int bb = item >> 1;
            const int half = (item & 1) * 64;
            float* gA = g_pA + (size_t)bb * 8192;
            float* gB = g_pB + (size_t)bb * 8192;
#pragma unroll
            for (int nt = 0; nt < 4; nt++) {
#pragma unroll
                for (int jj = 0; jj < 4; jj++) {
                    const int lr = half + ((jj >= 2) ? r2 : r1);
                    const int c = wn * 32 + nt * 8 + 2 * tig + (jj & 1);
                    const float v = vals[nt][jj];
                    {
                        int mt = lr >> 4, kt = c >> 3, rr = lr & 15, cc = c & 7;
                        gA[(mt * 8 + kt) * 128 + ((rr & 7) * 4 + (cc & 3)) * 4 +
                           (rr >> 3) + 2 * (cc >> 2)] = v;
                    }
                    {
                        int ntb = lr >> 3, kt = c >> 3, nn = lr & 7, kkb = c & 7;
                        gB[(ntb * 8 + kt) * 64 + (nn * 4 + (kkb & 3)) * 2 +
                           (kkb >> 2)] = v;
                    }
                }
            }
            __syncthreads();
            if (tid == 0) {
                __threadfence();
                atomicAdd(&g_done[bb], 1);
            }
            __syncthreads();

        } else {
            // ---------------- dist: one upper-tri 128x128 tile ---------------
            const int d = w - PREP_N - PROJ_N;
            const int bz = d / TRI;
            const int r = d - bz * TRI;
            // j-major enumeration: tile (i,j), i<=j, index = j(j+1)/2 + i
            int j = (int)((sqrtf(8.f * (float)r + 1.f) - 1.f) * 0.5f);
            while (j * (j + 1) / 2 > r) j--;
            while ((j + 1) * (j + 2) / 2 <= r) j++;
            const int i = r - j * (j + 1) / 2;

            const int ablk = bz * NTILE + i, bblk = bz * NTILE + j;

            if (tid == 0) {
                while (ld_acq(&g_done[ablk]) < 2 || ld_acq(&g_done[bblk]) < 2)
                    npause();
            }
            __syncthreads();

            const float4* gA = (const float4*)(g_pA + (size_t)ablk * 8192);
            const float4* gB = (const float4*)(g_pB + (size_t)bblk * 8192);
#pragma unroll
            for (int l = 0; l < 8; l++) {
                int idx = tid + l * 256;
                cpasync16(sbase + (uint32_t)idx * 16, gA + idx);
                cpasync16(sbase + 32768u + (uint32_t)idx * 16, gB + idx);
            }
            asm volatile("cp.async.commit_group;" ::: "memory");
            if (tid < 128) s_sqA[tid] = g_sq[ablk * 128 + tid];
            else           s_sqB[tid - 128] = g_sq[bblk * 128 + (tid - 128)];
            asm volatile("cp.async.wait_group 0;" ::: "memory");
            __syncthreads();

            const int wm = wid & 1, wn = wid >> 1;
            const float* As = smf;
            const float* Bs = smf + 8192;

            float acc[4][4][4];
#pragma unroll
            for (int a = 0; a < 4; a++)
#pragma unroll
                for (int b = 0; b < 4; b++)
#pragma unroll
                    for (int c = 0; c < 4; c++) acc[a][b][c] = 0.f;

#pragma unroll
            for (int kt = 0; kt < 8; kt++) {
                uint4 a[4];
                uint2 b[4];
#pragma unroll
                for (int mt = 0; mt < 4; mt++)
                    a[mt] = *(const uint4*)(As + ((wm * 4 + mt) * 8 + kt) * 128 +
                                            lane * 4);
#pragma unroll
                for (int nt = 0; nt < 4; nt++)
                    b[nt] = *(const uint2*)(Bs + ((wn * 4 + nt) * 8 + kt) * 64 +
                                            lane * 2);
#pragma unroll
                for (int mt = 0; mt < 4; mt++)
#pragma unroll
                    for (int nt = 0; nt < 4; nt++)
                        mma_tf32(acc[mt][nt], (const uint32_t*)&a[mt], b[nt].x,
                                 b[nt].y);
            }

#pragma unroll
            for (int mt = 0; mt < 4; mt++) {
                const int rl1 = wm * 64 + mt * 16 + gid, rl2 = rl1 + 8;
                const float sA1 = s_sqA[rl1], sA2 = s_sqA[rl2];
#pragma unroll
                for (int nt = 0; nt < 4; nt++) {
                    const int cl = wn * 32 + nt * 8 + 2 * tig;
                    const float sB0 = s_sqB[cl], sB1 = s_sqB[cl + 1];
                    acc[mt][nt][0] = fmaxf(sA1 + sB0 - 2.f * acc[mt][nt][0], 0.f);
                    acc[mt][nt][1] = fmaxf(sA1 + sB1 - 2.f * acc[mt][nt][1], 0.f);
                    acc[mt][nt][2] = fmaxf(sA2 + sB0 - 2.f * acc[mt][nt][2], 0.f);
                    acc[mt][nt][3] = fmaxf(sA2 + sB1 - 2.f * acc[mt][nt][3], 0.f);
                }
            }

#pragma unroll
            for (int mt = 0; mt < 4; mt++) {
                const int rl1 = wm * 64 + mt * 16 + gid;
                float* o1 = out + ((size_t)bz * SEQ + i * 128 + rl1) * SEQ +
                            j * 128;
                float* o2 = o1 + (size_t)8 * SEQ;
#pragma unroll
                for (int nt = 0; nt < 4; nt++) {
                    const int cl = wn * 32 + nt * 8 + 2 * tig;
                    __stcs((float2*)(o1 + cl),
                           make_float2(acc[mt][nt][0], acc[mt][nt][1]));
                    __stcs((float2*)(o2 + cl),
                           make_float2(acc[mt][nt][2], acc[mt][nt][3]));
                }
            }

            if (i != j) {
                __syncthreads();
                float* Ts = smf;
#pragma unroll
                for (int mt = 0; mt < 4; mt++) {
                    const int rl1 = wm * 64 + mt * 16 + gid, rl2 = rl1 + 8;
#pragma unroll
                    for (int nt = 0; nt < 4; nt++) {
                        const int cl = wn * 32 + nt * 8 + 2 * tig;
                        Ts[(cl + 0) * TS_STRIDE + rl1] = acc[mt][nt][0];
                        Ts[(cl + 1) * TS_STRIDE + rl1] = acc[mt][nt][1];
                        Ts[(cl + 0) * TS_STRIDE + rl2] = acc[mt][nt][2];
                        Ts[(cl + 1) * TS_STRIDE + rl2] = acc[mt][nt][3];
                    }
                }
                __syncthreads();
#pragma unroll
                for (int l = 0; l < 16; l++) {
                    int idx = tid + l * 256;
                    int c = idx >> 5, r4 = (idx & 31) << 2;
                    float4 v = *(const float4*)(Ts + c * TS_STRIDE + r4);
                    __stcs((float4*)(out + ((size_t)bz * SEQ + j * 128 + c) * SEQ +
                                     i * 128 + r4), v);
                }
            }
            __syncthreads();
        }
    }
}

// ============================================================
extern "C" void kernel_launch(void* const* d_in, const int* in_sizes, int n_in,
                              void* d_out, int out_size) {
    const float* x = (const float*)d_in[0];
    const float* proj = (const float*)d_in[1];
    float* out = (float*)d_out;

    reset_kernel<<<1, 160>>>();

    cudaFuncSetAttribute(fused_kernel,
                         cudaFuncAttributeMaxDynamicSharedMemorySize, FUSED_SMEM);
    fused_kernel<<<296, 256, FUSED_SMEM>>>(x, proj, out);
}